// round 4
// baseline (speedup 1.0000x reference)
#include <cuda_runtime.h>
#include <cstdint>

#define BB 16
#define NN 1024
#define FIN 64
#define HH 256
#define ROWS 32
#define JCH 32
#define NCH (NN / JCH)

// ---------------- scratch (no allocs allowed) ----------------
__device__ float g_x[BB * NN * HH];   // 16 MB
__device__ float g_h[BB * NN * HH];   // 16 MB
__device__ float g_s1[BB * NN];
__device__ float g_s2[BB * NN];

typedef unsigned long long u64;

__device__ __forceinline__ u64 pack2(float x) {
    u64 r; asm("mov.b64 %0, {%1, %1};" : "=l"(r) : "f"(x)); return r;
}
__device__ __forceinline__ void ffma2(u64& d, u64 a, u64 b) {
    asm("fma.rn.f32x2 %0, %1, %2, %0;" : "+l"(d) : "l"(a), "l"(b));
}
__device__ __forceinline__ float2 unpack2(u64 v) {
    float2 r; asm("mov.b64 {%0, %1}, %2;" : "=f"(r.x), "=f"(r.y) : "l"(v)); return r;
}
__device__ __forceinline__ float leaky(float x) { return x >= 0.f ? x : 0.2f * x; }

__device__ __forceinline__ void cpasync16(uint32_t dst, const void* src) {
    asm volatile("cp.async.cg.shared.global [%0], [%1], 16;" :: "r"(dst), "l"(src));
}
#define CP_COMMIT() asm volatile("cp.async.commit_group;")
#define CP_WAIT1()  asm volatile("cp.async.wait_group 1;")

// h_s per-cx stride: JCH*8 + 12 floats = 268 floats = 1072 B (1072 % 128 == 48 -> conflict-free)
#define HS_STRIDE_F 268
#define HS_BUF_F    (32 * HS_STRIDE_F)      // 8576 floats per buffer

// ============================================================================
// embed: out[M,256] = nf[M,64] @ W[64,256] + b
// ============================================================================
__global__ __launch_bounds__(128) void embed_kernel(
    const float* __restrict__ nf, const float* __restrict__ W,
    const float* __restrict__ bias, float* __restrict__ out)
{
    __shared__ float xs[4 * FIN * 4];
    const int row0 = blockIdx.x * 16;
    const int tid = threadIdx.x;

#pragma unroll
    for (int it = 0; it < 2; it++) {
        int idx = it * 128 + tid;
        int g = idx >> 6, k = idx & 63;
        float4 v;
        v.x = nf[(size_t)(row0 + 4 * g + 0) * FIN + k];
        v.y = nf[(size_t)(row0 + 4 * g + 1) * FIN + k];
        v.z = nf[(size_t)(row0 + 4 * g + 2) * FIN + k];
        v.w = nf[(size_t)(row0 + 4 * g + 3) * FIN + k];
        *(float4*)(xs + g * (FIN * 4) + k * 4) = v;
    }
    __syncthreads();

    u64 accA[8], accB[8];
#pragma unroll
    for (int p = 0; p < 8; p++) { accA[p] = 0ULL; accB[p] = 0ULL; }

    const int c = tid;
    float wA[4], wB[4];
#pragma unroll
    for (int u = 0; u < 4; u++) { wA[u] = W[u * HH + c]; wB[u] = W[u * HH + c + 128]; }

    for (int kt = 0; kt < FIN; kt += 4) {
        float cAv[4], cBv[4];
#pragma unroll
        for (int u = 0; u < 4; u++) { cAv[u] = wA[u]; cBv[u] = wB[u]; }
        if (kt + 4 < FIN) {
#pragma unroll
            for (int u = 0; u < 4; u++) {
                wA[u] = W[(kt + 4 + u) * HH + c];
                wB[u] = W[(kt + 4 + u) * HH + c + 128];
            }
        }
#pragma unroll
        for (int u = 0; u < 4; u++) {
            int k = kt + u;
            u64 h2a = pack2(cAv[u]);
            u64 h2b = pack2(cBv[u]);
#pragma unroll
            for (int g = 0; g < 4; g++) {
                ulonglong2 q = *(const ulonglong2*)(xs + g * (FIN * 4) + k * 4);
                ffma2(accA[2 * g], q.x, h2a); ffma2(accA[2 * g + 1], q.y, h2a);
                ffma2(accB[2 * g], q.x, h2b); ffma2(accB[2 * g + 1], q.y, h2b);
            }
        }
    }
    const float bA = bias[c], bBv = bias[c + 128];
    float* ob = out + (size_t)row0 * HH + c;
#pragma unroll
    for (int p = 0; p < 8; p++) {
        float2 vA = unpack2(accA[p]);
        float2 vB = unpack2(accB[p]);
        ob[(size_t)(2 * p) * HH]           = vA.x + bA;
        ob[(size_t)(2 * p + 1) * HH]       = vA.y + bA;
        ob[(size_t)(2 * p) * HH + 128]     = vB.x + bBv;
        ob[(size_t)(2 * p + 1) * HH + 128] = vB.y + bBv;
    }
}

// ============================================================================
// gemm256 + fused s1/s2
// ============================================================================
__global__ __launch_bounds__(128) void gemm_s1s2_kernel(
    const float* __restrict__ X, const float* __restrict__ W,
    const float* __restrict__ a1, const float* __restrict__ a2,
    float* __restrict__ hout, float* __restrict__ s1o, float* __restrict__ s2o)
{
    __shared__ float xs[4 * HH * 4];
    __shared__ float red[128];
    const int row0 = blockIdx.x * 16;
    const int tid = threadIdx.x;
    const int lane = tid & 31, wid = tid >> 5;

#pragma unroll
    for (int it = 0; it < 8; it++) {
        int idx = it * 128 + tid;
        int g = idx >> 8, k = idx & 255;
        float4 v;
        v.x = X[(size_t)(row0 + 4 * g + 0) * HH + k];
        v.y = X[(size_t)(row0 + 4 * g + 1) * HH + k];
        v.z = X[(size_t)(row0 + 4 * g + 2) * HH + k];
        v.w = X[(size_t)(row0 + 4 * g + 3) * HH + k];
        *(float4*)(xs + g * (HH * 4) + k * 4) = v;
    }
    __syncthreads();

    u64 accA[8], accB[8];
#pragma unroll
    for (int p = 0; p < 8; p++) { accA[p] = 0ULL; accB[p] = 0ULL; }

    const int c = tid;
    float wA[4], wB[4];
#pragma unroll
    for (int u = 0; u < 4; u++) { wA[u] = W[u * HH + c]; wB[u] = W[u * HH + c + 128]; }

    for (int kt = 0; kt < HH; kt += 4) {
        float cAv[4], cBv[4];
#pragma unroll
        for (int u = 0; u < 4; u++) { cAv[u] = wA[u]; cBv[u] = wB[u]; }
        if (kt + 4 < HH) {
#pragma unroll
            for (int u = 0; u < 4; u++) {
                wA[u] = W[(kt + 4 + u) * HH + c];
                wB[u] = W[(kt + 4 + u) * HH + c + 128];
            }
        }
#pragma unroll
        for (int u = 0; u < 4; u++) {
            int k = kt + u;
            u64 h2a = pack2(cAv[u]);
            u64 h2b = pack2(cBv[u]);
#pragma unroll
            for (int g = 0; g < 4; g++) {
                ulonglong2 q = *(const ulonglong2*)(xs + g * (HH * 4) + k * 4);
                ffma2(accA[2 * g], q.x, h2a); ffma2(accA[2 * g + 1], q.y, h2a);
                ffma2(accB[2 * g], q.x, h2b); ffma2(accB[2 * g + 1], q.y, h2b);
            }
        }
    }

    const float a1A = a1[c], a1B = a1[c + 128];
    const float a2A = a2[c], a2B = a2[c + 128];
    float s1p[16], s2p[16];
    float* ob = hout + (size_t)row0 * HH + c;
#pragma unroll
    for (int p = 0; p < 8; p++) {
        float2 vA = unpack2(accA[p]);
        float2 vB = unpack2(accB[p]);
        ob[(size_t)(2 * p) * HH]           = vA.x;
        ob[(size_t)(2 * p + 1) * HH]       = vA.y;
        ob[(size_t)(2 * p) * HH + 128]     = vB.x;
        ob[(size_t)(2 * p + 1) * HH + 128] = vB.y;
        s1p[2 * p]     = vA.x * a1A + vB.x * a1B;
        s1p[2 * p + 1] = vA.y * a1A + vB.y * a1B;
        s2p[2 * p]     = vA.x * a2A + vB.x * a2B;
        s2p[2 * p + 1] = vA.y * a2A + vB.y * a2B;
    }
#pragma unroll
    for (int r = 0; r < 16; r++) {
#pragma unroll
        for (int o = 16; o; o >>= 1) {
            s1p[r] += __shfl_xor_sync(0xffffffffu, s1p[r], o);
            s2p[r] += __shfl_xor_sync(0xffffffffu, s2p[r], o);
        }
        if (lane == 0) { red[r * 4 + wid] = s1p[r]; red[64 + r * 4 + wid] = s2p[r]; }
    }
    __syncthreads();
    if (tid < 32) {
        int r = tid & 15;
        int base = (tid < 16) ? 0 : 64;
        float s = red[base + r * 4] + red[base + r * 4 + 1] + red[base + r * 4 + 2] + red[base + r * 4 + 3];
        if (tid < 16) s1o[row0 + r] = s; else s2o[row0 + r] = s;
    }
}

// ============================================================================
// attention: out = relu( softmax_row( mask( leaky(s1_i + s2_j) ) ) @ h )
// 32 rows/block, 128 threads. Thread tile: 8 rows (warp=row-group) x 8 cols.
// att_s[j][32 rows] with 16B-slot XOR swizzle; h staged via cp.async chunks.
// ============================================================================
__global__ __launch_bounds__(128, 1) void att_kernel(
    const float* __restrict__ adj, const float* __restrict__ h,
    const float* __restrict__ s1, const float* __restrict__ s2,
    float* __restrict__ out)
{
    extern __shared__ float sm[];
    float* att_s = sm;                                     // 32768 floats (128 KB)
    float* h_s   = sm + 32768;                             // 2 * 8576 floats
    float* s1mi  = sm + 32768 + 2 * HS_BUF_F;              // 64 floats (s1, mi pairs)
    float* rinv  = s1mi + 64;                              // 32
    float* red   = rinv + 32;                              // 128
    float* s2mx  = red + 128;                              // 4

    const int b = blockIdx.y;
    const int i0 = blockIdx.x * ROWS;
    const int tid = threadIdx.x;
    const int lane = tid & 31, rg = tid >> 5;
    const int cx = lane;

    const float* hgl = h + (size_t)b * NN * HH;
    uint32_t hs_base = (uint32_t)__cvta_generic_to_shared(h_s);

    // kick off h chunk 0 early (overlaps phase A)
    {
        int cxl = tid & 31;
        int j0 = (tid >> 5) * 8;
#pragma unroll
        for (int k = 0; k < 8; k++) {
            int jj = j0 + k;
            const float* src = hgl + (size_t)jj * HH + cxl * 8;
            uint32_t dst = hs_base + (uint32_t)(cxl * HS_STRIDE_F + jj * 8) * 4u;
            cpasync16(dst, src);
            cpasync16(dst + 16, src + 4);
        }
        CP_COMMIT();
    }

    // ---- s2 load + block max ----
    const float* s2b = s2 + b * NN;
    float s2v[8];
    float mx = -3.4e38f;
#pragma unroll
    for (int u = 0; u < 8; u++) { s2v[u] = s2b[u * 128 + tid]; mx = fmaxf(mx, s2v[u]); }
#pragma unroll
    for (int o = 16; o; o >>= 1) mx = fmaxf(mx, __shfl_xor_sync(0xffffffffu, mx, o));
    if (lane == 0) s2mx[rg] = mx;
    __syncthreads();
    const float s2max = fmaxf(fmaxf(s2mx[0], s2mx[1]), fmaxf(s2mx[2], s2mx[3]));
    if (tid < 32) {
        float s1v = s1[b * NN + i0 + tid];
        s1mi[2 * tid]     = s1v;
        s1mi[2 * tid + 1] = leaky(s1v + s2max);
    }
    __syncthreads();

    // ---- phase A: probs into att_s, row-sum partials ----
    float sums[32];
#pragma unroll
    for (int r = 0; r < 32; r++) sums[r] = 0.f;

    const float* adjb = adj + ((size_t)b * NN + i0) * NN;
#pragma unroll 1
    for (int u = 0; u < 8; u++) {
        const int j = u * 128 + tid;
        const float s2j = s2v[u];
        const uint32_t sw = (uint32_t)((j & 7) << 4);
        char* jrow = (char*)att_s + (size_t)j * 128;
#pragma unroll
        for (int rq = 0; rq < 8; rq++) {
            float4 pv;
            float p;
            {
                float2 sm2 = *(const float2*)(s1mi + 2 * (4 * rq + 0));
                float a = adjb[(size_t)(4 * rq + 0) * NN + j];
                p = (a > 0.f) ? __expf(leaky(sm2.x + s2j) - sm2.y) : 0.f;
                pv.x = p; sums[4 * rq + 0] += p;
            }
            {
                float2 sm2 = *(const float2*)(s1mi + 2 * (4 * rq + 1));
                float a = adjb[(size_t)(4 * rq + 1) * NN + j];
                p = (a > 0.f) ? __expf(leaky(sm2.x + s2j) - sm2.y) : 0.f;
                pv.y = p; sums[4 * rq + 1] += p;
            }
            {
                float2 sm2 = *(const float2*)(s1mi + 2 * (4 * rq + 2));
                float a = adjb[(size_t)(4 * rq + 2) * NN + j];
                p = (a > 0.f) ? __expf(leaky(sm2.x + s2j) - sm2.y) : 0.f;
                pv.z = p; sums[4 * rq + 2] += p;
            }
            {
                float2 sm2 = *(const float2*)(s1mi + 2 * (4 * rq + 3));
                float a = adjb[(size_t)(4 * rq + 3) * NN + j];
                p = (a > 0.f) ? __expf(leaky(sm2.x + s2j) - sm2.y) : 0.f;
                pv.w = p; sums[4 * rq + 3] += p;
            }
            *(float4*)(jrow + (((uint32_t)(rq * 16)) ^ sw)) = pv;
        }
    }

    // row-sum reduce: butterfly per row, lane r keeps row r's warp total
    float myv = 0.f;
#pragma unroll
    for (int r = 0; r < 32; r++) {
        float v = sums[r];
#pragma unroll
        for (int o = 16; o; o >>= 1) v += __shfl_xor_sync(0xffffffffu, v, o);
        if (lane == r) myv = v;
    }
    red[rg * 32 + lane] = myv;
    __syncthreads();
    if (tid < 32) rinv[tid] = 1.0f / (red[tid] + red[32 + tid] + red[64 + tid] + red[96 + tid]);

    // ---- phase B: C[32,256] = att[32,1024] @ h[1024,256] ----
    u64 acc[4][8];
#pragma unroll
    for (int p = 0; p < 4; p++)
#pragma unroll
        for (int q = 0; q < 8; q++) acc[p][q] = 0ULL;

    const uint32_t ro0 = (uint32_t)(rg * 32);
    const uint32_t ro1 = ro0 + 16;

    for (int c = 0; c < NCH; c++) {
        if (c + 1 < NCH) {
            int cxl = tid & 31;
            int j0 = (tid >> 5) * 8;
            uint32_t buf = hs_base + (uint32_t)(((c + 1) & 1) * HS_BUF_F) * 4u;
#pragma unroll
            for (int k = 0; k < 8; k++) {
                int jj = j0 + k;
                const float* src = hgl + (size_t)((c + 1) * JCH + jj) * HH + cxl * 8;
                uint32_t dst = buf + (uint32_t)(cxl * HS_STRIDE_F + jj * 8) * 4u;
                cpasync16(dst, src);
                cpasync16(dst + 16, src + 4);
            }
        }
        CP_COMMIT();
        CP_WAIT1();
        __syncthreads();

        const char* hcur = (const char*)(h_s + (c & 1) * HS_BUF_F) + cx * (HS_STRIDE_F * 4);

#pragma unroll 4
        for (int jj = 0; jj < JCH; jj++) {
            const int j = c * JCH + jj;
            const uint32_t sw = (uint32_t)((j & 7) << 4);
            const char* ab = (const char*)att_s + (size_t)j * 128;
            ulonglong2 a01 = *(const ulonglong2*)(ab + (ro0 ^ sw));
            ulonglong2 a23 = *(const ulonglong2*)(ab + (ro1 ^ sw));
            float4 h0 = *(const float4*)(hcur + jj * 32);
            float4 h1 = *(const float4*)(hcur + jj * 32 + 16);
            u64 hp;
            hp = pack2(h0.x);
            ffma2(acc[0][0], a01.x, hp); ffma2(acc[1][0], a01.y, hp);
            ffma2(acc[2][0], a23.x, hp); ffma2(acc[3][0], a23.y, hp);
            hp = pack2(h0.y);
            ffma2(acc[0][1], a01.x, hp); ffma2(acc[1][1], a01.y, hp);
            ffma2(acc[2][1], a23.x, hp); ffma2(acc[3][1], a23.y, hp);
            hp = pack2(h0.z);
            ffma2(acc[0][2], a01.x, hp); ffma2(acc[1][2], a01.y, hp);
            ffma2(acc[2][2], a23.x, hp); ffma2(acc[3][2], a23.y, hp);
            hp = pack2(h0.w);
            ffma2(acc[0][3], a01.x, hp); ffma2(acc[1][3], a01.y, hp);
            ffma2(acc[2][3], a23.x, hp); ffma2(acc[3][3], a23.y, hp);
            hp = pack2(h1.x);
            ffma2(acc[0][4], a01.x, hp); ffma2(acc[1][4], a01.y, hp);
            ffma2(acc[2][4], a23.x, hp); ffma2(acc[3][4], a23.y, hp);
            hp = pack2(h1.y);
            ffma2(acc[0][5], a01.x, hp); ffma2(acc[1][5], a01.y, hp);
            ffma2(acc[2][5], a23.x, hp); ffma2(acc[3][5], a23.y, hp);
            hp = pack2(h1.z);
            ffma2(acc[0][6], a01.x, hp); ffma2(acc[1][6], a01.y, hp);
            ffma2(acc[2][6], a23.x, hp); ffma2(acc[3][6], a23.y, hp);
            hp = pack2(h1.w);
            ffma2(acc[0][7], a01.x, hp); ffma2(acc[1][7], a01.y, hp);
            ffma2(acc[2][7], a23.x, hp); ffma2(acc[3][7], a23.y, hp);
        }
        __syncthreads();
    }

    // ---- epilogue: normalize + ReLU + store ----
    float* ob = out + ((size_t)b * NN + i0 + rg * 8) * HH + cx * 8;
#pragma unroll
    for (int rp = 0; rp < 4; rp++) {
        const float ri0 = rinv[rg * 8 + 2 * rp];
        const float ri1 = rinv[rg * 8 + 2 * rp + 1];
        float4 e0, e1, o0, o1;
        float2 v;
        v = unpack2(acc[rp][0]); e0.x = fmaxf(v.x * ri0, 0.f); o0.x = fmaxf(v.y * ri1, 0.f);
        v = unpack2(acc[rp][1]); e0.y = fmaxf(v.x * ri0, 0.f); o0.y = fmaxf(v.y * ri1, 0.f);
        v = unpack2(acc[rp][2]); e0.z = fmaxf(v.x * ri0, 0.f); o0.z = fmaxf(v.y * ri1, 0.f);
        v = unpack2(acc[rp][3]); e0.w = fmaxf(v.x * ri0, 0.f); o0.w = fmaxf(v.y * ri1, 0.f);
        v = unpack2(acc[rp][4]); e1.x = fmaxf(v.x * ri0, 0.f); o1.x = fmaxf(v.y * ri1, 0.f);
        v = unpack2(acc[rp][5]); e1.y = fmaxf(v.x * ri0, 0.f); o1.y = fmaxf(v.y * ri1, 0.f);
        v = unpack2(acc[rp][6]); e1.z = fmaxf(v.x * ri0, 0.f); o1.z = fmaxf(v.y * ri1, 0.f);
        v = unpack2(acc[rp][7]); e1.w = fmaxf(v.x * ri0, 0.f); o1.w = fmaxf(v.y * ri1, 0.f);
        float* r0p = ob + (size_t)(2 * rp) * HH;
        float* r1p = ob + (size_t)(2 * rp + 1) * HH;
        *(float4*)(r0p)     = e0;
        *(float4*)(r0p + 4) = e1;
        *(float4*)(r1p)     = o0;
        *(float4*)(r1p + 4) = o1;
    }
}

// ---------------- pool (mean+max over N) + 2-layer MLP ----------------
__global__ __launch_bounds__(256) void pool_mlp_kernel(
    const float* __restrict__ x, const float* __restrict__ W1,
    const float* __restrict__ b1, const float* __restrict__ W2,
    const float* __restrict__ b2, float* __restrict__ gout)
{
    __shared__ float g0[HH];
    __shared__ float t1[HH];
    const int b = blockIdx.x, c = threadIdx.x;
    const float* xb = x + (size_t)b * NN * HH + c;

    float s = 0.f, m = -3.4e38f;
#pragma unroll 8
    for (int n = 0; n < NN; n++) {
        float v = xb[(size_t)n * HH];
        s += v;
        m = fmaxf(m, v);
    }
    g0[c] = s * (1.0f / NN) + m;
    __syncthreads();

    float a = b1[c];
#pragma unroll 4
    for (int k = 0; k < HH; k++) a += g0[k] * W1[k * HH + c];
    t1[c] = fmaxf(a, 0.f);
    __syncthreads();

    float a2 = b2[c];
#pragma unroll 4
    for (int k = 0; k < HH; k++) a2 += t1[k] * W2[k * HH + c];
    gout[b * HH + c] = a2;
}

// ---------------- launch ----------------
extern "C" void kernel_launch(void* const* d_in, const int* in_sizes, int n_in,
                              void* d_out, int out_size)
{
    const float* nf   = (const float*)d_in[0];
    const float* adj  = (const float*)d_in[1];
    const float* embW = (const float*)d_in[2];
    const float* embB = (const float*)d_in[3];
    const float* W0   = (const float*)d_in[4];
    const float* a10  = (const float*)d_in[5];
    const float* a20  = (const float*)d_in[6];
    const float* W1   = (const float*)d_in[7];
    const float* a11  = (const float*)d_in[8];
    const float* a21  = (const float*)d_in[9];
    const float* gW1  = (const float*)d_in[10];
    const float* gb1  = (const float*)d_in[11];
    const float* gW2  = (const float*)d_in[12];
    const float* gb2  = (const float*)d_in[13];

    float* out  = (float*)d_out;
    float* xout = out;                              // [B,N,H]
    float* gout = out + (size_t)BB * NN * HH;       // [B,H]

    float *xb, *hb, *s1b, *s2b;
    cudaGetSymbolAddress((void**)&xb,  g_x);
    cudaGetSymbolAddress((void**)&hb,  g_h);
    cudaGetSymbolAddress((void**)&s1b, g_s1);
    cudaGetSymbolAddress((void**)&s2b, g_s2);

    // att smem: 128KB att + 2*34304B h stage + 912B small = ~198KB
    const int att_smem = (32768 + 2 * HS_BUF_F + 64 + 32 + 128 + 4) * 4;
    cudaFuncSetAttribute(att_kernel, cudaFuncAttributeMaxDynamicSharedMemorySize, att_smem);

    const int mrows = BB * NN;
    dim3 blk128(128);

    embed_kernel<<<mrows / 16, blk128>>>(nf, embW, embB, xb);

    // layer 0
    gemm_s1s2_kernel<<<mrows / 16, blk128>>>(xb, W0, a10, a20, hb, s1b, s2b);
    att_kernel<<<dim3(NN / ROWS, BB), blk128, att_smem>>>(adj, hb, s1b, s2b, xb);

    // layer 1
    gemm_s1s2_kernel<<<mrows / 16, blk128>>>(xb, W1, a11, a21, hb, s1b, s2b);
    att_kernel<<<dim3(NN / ROWS, BB), blk128, att_smem>>>(adj, hb, s1b, s2b, xout);

    // pooling + MLP head
    pool_mlp_kernel<<<BB, 256>>>(xout, gW1, gb1, gW2, gb2, gout);
}

// round 5
// speedup vs baseline: 1.5937x; 1.5937x over previous
#include <cuda_runtime.h>
#include <cstdint>

#define BB 16
#define NN 1024
#define FIN 64
#define HH 256

// ---------------- scratch (no allocs allowed) ----------------
__device__ float g_x[BB * NN * HH];   // 16 MB
__device__ float g_h[BB * NN * HH];   // 16 MB
__device__ float g_s1[BB * NN];
__device__ float g_s2[BB * NN];
__device__ uint32_t g_mask[BB * NN * (NN / 32)];   // 2 MB bit-packed adj
__device__ float g_pool[BB * 8 * 2 * HH];          // pooling partials

typedef unsigned long long u64;

__device__ __forceinline__ u64 pack2(float x) {
    u64 r; asm("mov.b64 %0, {%1, %1};" : "=l"(r) : "f"(x)); return r;
}
__device__ __forceinline__ void ffma2(u64& d, u64 a, u64 b) {
    asm("fma.rn.f32x2 %0, %1, %2, %0;" : "+l"(d) : "l"(a), "l"(b));
}
__device__ __forceinline__ float2 unpack2(u64 v) {
    float2 r; asm("mov.b64 {%0, %1}, %2;" : "=f"(r.x), "=f"(r.y) : "l"(v)); return r;
}
__device__ __forceinline__ float leaky(float x) { return x >= 0.f ? x : 0.2f * x; }

// ============================================================================
// pack_adj: adj float(0/1)[B*N*N] -> bitmask (1 bit per entry)
// ============================================================================
__global__ __launch_bounds__(256) void pack_adj_kernel(
    const float* __restrict__ adj, uint32_t* __restrict__ mask)
{
    const int idx = blockIdx.x * 256 + threadIdx.x;
    const float v = adj[idx];
    const unsigned bal = __ballot_sync(0xffffffffu, v > 0.f);
    if ((threadIdx.x & 31) == 0) mask[idx >> 5] = bal;
}

// ============================================================================
// embed: out[M,256] = nf[M,64] @ W[64,256] + b
// ============================================================================
__global__ __launch_bounds__(128) void embed_kernel(
    const float* __restrict__ nf, const float* __restrict__ W,
    const float* __restrict__ bias, float* __restrict__ out)
{
    __shared__ float xs[4 * FIN * 4];
    const int row0 = blockIdx.x * 16;
    const int tid = threadIdx.x;

#pragma unroll
    for (int it = 0; it < 2; it++) {
        int idx = it * 128 + tid;
        int g = idx >> 6, k = idx & 63;
        float4 v;
        v.x = nf[(size_t)(row0 + 4 * g + 0) * FIN + k];
        v.y = nf[(size_t)(row0 + 4 * g + 1) * FIN + k];
        v.z = nf[(size_t)(row0 + 4 * g + 2) * FIN + k];
        v.w = nf[(size_t)(row0 + 4 * g + 3) * FIN + k];
        *(float4*)(xs + g * (FIN * 4) + k * 4) = v;
    }
    __syncthreads();

    u64 accA[8], accB[8];
#pragma unroll
    for (int p = 0; p < 8; p++) { accA[p] = 0ULL; accB[p] = 0ULL; }

    const int c = tid;
    float wA[4], wB[4];
#pragma unroll
    for (int u = 0; u < 4; u++) { wA[u] = W[u * HH + c]; wB[u] = W[u * HH + c + 128]; }

    for (int kt = 0; kt < FIN; kt += 4) {
        float cAv[4], cBv[4];
#pragma unroll
        for (int u = 0; u < 4; u++) { cAv[u] = wA[u]; cBv[u] = wB[u]; }
        if (kt + 4 < FIN) {
#pragma unroll
            for (int u = 0; u < 4; u++) {
                wA[u] = W[(kt + 4 + u) * HH + c];
                wB[u] = W[(kt + 4 + u) * HH + c + 128];
            }
        }
#pragma unroll
        for (int u = 0; u < 4; u++) {
            int k = kt + u;
            u64 h2a = pack2(cAv[u]);
            u64 h2b = pack2(cBv[u]);
#pragma unroll
            for (int g = 0; g < 4; g++) {
                ulonglong2 q = *(const ulonglong2*)(xs + g * (FIN * 4) + k * 4);
                ffma2(accA[2 * g], q.x, h2a); ffma2(accA[2 * g + 1], q.y, h2a);
                ffma2(accB[2 * g], q.x, h2b); ffma2(accB[2 * g + 1], q.y, h2b);
            }
        }
    }
    const float bA = bias[c], bBv = bias[c + 128];
    float* ob = out + (size_t)row0 * HH + c;
#pragma unroll
    for (int p = 0; p < 8; p++) {
        float2 vA = unpack2(accA[p]);
        float2 vB = unpack2(accB[p]);
        ob[(size_t)(2 * p) * HH]           = vA.x + bA;
        ob[(size_t)(2 * p + 1) * HH]       = vA.y + bA;
        ob[(size_t)(2 * p) * HH + 128]     = vB.x + bBv;
        ob[(size_t)(2 * p + 1) * HH + 128] = vB.y + bBv;
    }
}

// ============================================================================
// gemm256 + fused s1/s2
// ============================================================================
__global__ __launch_bounds__(128) void gemm_s1s2_kernel(
    const float* __restrict__ X, const float* __restrict__ W,
    const float* __restrict__ a1, const float* __restrict__ a2,
    float* __restrict__ hout, float* __restrict__ s1o, float* __restrict__ s2o)
{
    __shared__ float xs[4 * HH * 4];
    __shared__ float red[128];
    const int row0 = blockIdx.x * 16;
    const int tid = threadIdx.x;
    const int lane = tid & 31, wid = tid >> 5;

#pragma unroll
    for (int it = 0; it < 8; it++) {
        int idx = it * 128 + tid;
        int g = idx >> 8, k = idx & 255;
        float4 v;
        v.x = X[(size_t)(row0 + 4 * g + 0) * HH + k];
        v.y = X[(size_t)(row0 + 4 * g + 1) * HH + k];
        v.z = X[(size_t)(row0 + 4 * g + 2) * HH + k];
        v.w = X[(size_t)(row0 + 4 * g + 3) * HH + k];
        *(float4*)(xs + g * (HH * 4) + k * 4) = v;
    }
    __syncthreads();

    u64 accA[8], accB[8];
#pragma unroll
    for (int p = 0; p < 8; p++) { accA[p] = 0ULL; accB[p] = 0ULL; }

    const int c = tid;
    float wA[4], wB[4];
#pragma unroll
    for (int u = 0; u < 4; u++) { wA[u] = W[u * HH + c]; wB[u] = W[u * HH + c + 128]; }

    for (int kt = 0; kt < HH; kt += 4) {
        float cAv[4], cBv[4];
#pragma unroll
        for (int u = 0; u < 4; u++) { cAv[u] = wA[u]; cBv[u] = wB[u]; }
        if (kt + 4 < HH) {
#pragma unroll
            for (int u = 0; u < 4; u++) {
                wA[u] = W[(kt + 4 + u) * HH + c];
                wB[u] = W[(kt + 4 + u) * HH + c + 128];
            }
        }
#pragma unroll
        for (int u = 0; u < 4; u++) {
            int k = kt + u;
            u64 h2a = pack2(cAv[u]);
            u64 h2b = pack2(cBv[u]);
#pragma unroll
            for (int g = 0; g < 4; g++) {
                ulonglong2 q = *(const ulonglong2*)(xs + g * (HH * 4) + k * 4);
                ffma2(accA[2 * g], q.x, h2a); ffma2(accA[2 * g + 1], q.y, h2a);
                ffma2(accB[2 * g], q.x, h2b); ffma2(accB[2 * g + 1], q.y, h2b);
            }
        }
    }

    const float a1A = a1[c], a1B = a1[c + 128];
    const float a2A = a2[c], a2B = a2[c + 128];
    float s1p[16], s2p[16];
    float* ob = hout + (size_t)row0 * HH + c;
#pragma unroll
    for (int p = 0; p < 8; p++) {
        float2 vA = unpack2(accA[p]);
        float2 vB = unpack2(accB[p]);
        ob[(size_t)(2 * p) * HH]           = vA.x;
        ob[(size_t)(2 * p + 1) * HH]       = vA.y;
        ob[(size_t)(2 * p) * HH + 128]     = vB.x;
        ob[(size_t)(2 * p + 1) * HH + 128] = vB.y;
        s1p[2 * p]     = vA.x * a1A + vB.x * a1B;
        s1p[2 * p + 1] = vA.y * a1A + vB.y * a1B;
        s2p[2 * p]     = vA.x * a2A + vB.x * a2B;
        s2p[2 * p + 1] = vA.y * a2A + vB.y * a2B;
    }
#pragma unroll
    for (int r = 0; r < 16; r++) {
#pragma unroll
        for (int o = 16; o; o >>= 1) {
            s1p[r] += __shfl_xor_sync(0xffffffffu, s1p[r], o);
            s2p[r] += __shfl_xor_sync(0xffffffffu, s2p[r], o);
        }
        if (lane == 0) { red[r * 4 + wid] = s1p[r]; red[64 + r * 4 + wid] = s2p[r]; }
    }
    __syncthreads();
    if (tid < 32) {
        int r = tid & 15;
        int base = (tid < 16) ? 0 : 64;
        float s = red[base + r * 4] + red[base + r * 4 + 1] + red[base + r * 4 + 2] + red[base + r * 4 + 3];
        if (tid < 16) s1o[row0 + r] = s; else s2o[row0 + r] = s;
    }
}

// ============================================================================
// attention: out = relu( softmax_row( mask( leaky(s1_i + s2_j) ) ) @ h )
// 16 rows/block, 128 threads. adj replaced by bit-packed mask (L2-resident).
// h prefetched 8-deep from global. att smem [g][j][q] row-quads (64 KB).
// ============================================================================
__global__ __launch_bounds__(128) void att_kernel(
    const uint32_t* __restrict__ mask, const float* __restrict__ h,
    const float* __restrict__ s1, const float* __restrict__ s2,
    float* __restrict__ out)
{
    extern __shared__ float att[];        // 16384 floats (64KB)
    __shared__ uint32_t msk[16 * 32];     // 2KB: 16 rows x 32 words
    __shared__ float red[64];
    __shared__ float rinv[16];
    __shared__ float s2max_sh;

    const int b = blockIdx.y;
    const int i0 = blockIdx.x * 16;
    const int tid = threadIdx.x;
    const int lane = tid & 31, wid = tid >> 5;

    // load this block's 16 mask rows (512 words)
    {
        const uint4* mg = (const uint4*)(mask + ((size_t)b * NN + i0) * 32);
        ((uint4*)msk)[tid] = mg[tid];
    }

    const float* s2b = s2 + b * NN;
    float s2v[8];
    float m = -3.4e38f;
#pragma unroll
    for (int u = 0; u < 8; u++) { s2v[u] = s2b[u * 128 + tid]; m = fmaxf(m, s2v[u]); }
#pragma unroll
    for (int o = 16; o; o >>= 1) m = fmaxf(m, __shfl_xor_sync(0xffffffffu, m, o));
    if (lane == 0) red[wid] = m;
    __syncthreads();
    if (tid == 0) s2max_sh = fmaxf(fmaxf(red[0], red[1]), fmaxf(red[2], red[3]));
    __syncthreads();
    const float s2max = s2max_sh;

    // -------- phase A: unnormalized probs into att, rowsum partials --------
#pragma unroll
    for (int g = 0; g < 4; g++) {
        float s1v[4], mi[4], sum[4];
#pragma unroll
        for (int q = 0; q < 4; q++) {
            s1v[q] = s1[b * NN + i0 + 4 * g + q];
            mi[q] = leaky(s1v[q] + s2max);
            sum[q] = 0.f;
        }
#pragma unroll 2
        for (int u = 0; u < 8; u++) {
            int j = u * 128 + tid;
            float s2j = s2v[u];
            float4 pv;
#pragma unroll
            for (int q = 0; q < 4; q++) {
                uint32_t mw = msk[(4 * g + q) * 32 + u * 4 + wid];  // broadcast LDS
                float e = leaky(s1v[q] + s2j);
                float p = ((mw >> lane) & 1u) ? __expf(e - mi[q]) : 0.f;
                ((float*)&pv)[q] = p;
                sum[q] += p;
            }
            *(float4*)(att + g * 4096 + j * 4) = pv;   // conflict-free STS.128
        }
#pragma unroll
        for (int q = 0; q < 4; q++) {
#pragma unroll
            for (int o = 16; o; o >>= 1) sum[q] += __shfl_xor_sync(0xffffffffu, sum[q], o);
            if (lane == 0) red[(4 * g + q) * 4 + wid] = sum[q];
        }
    }
    __syncthreads();
    if (tid < 16) {
        float s = red[tid * 4] + red[tid * 4 + 1] + red[tid * 4 + 2] + red[tid * 4 + 3];
        rinv[tid] = 1.0f / s;
    }
    __syncthreads();

    // -------- phase B: C[16,256] = att[16,1024] @ h[1024,256], 8-deep prefetch --
    u64 accA[8], accB[8];
#pragma unroll
    for (int p = 0; p < 8; p++) { accA[p] = 0ULL; accB[p] = 0ULL; }

    const float* hpA = h + (size_t)b * NN * HH + tid;      // col c = tid
    const float* hpB = hpA + 128;                          // col c+128
    float hA[8], hB[8];
#pragma unroll
    for (int u = 0; u < 8; u++) { hA[u] = hpA[(size_t)u * HH]; hB[u] = hpB[(size_t)u * HH]; }

    for (int jt = 0; jt < NN; jt += 8) {
        const bool pf = (jt + 8) < NN;
#pragma unroll
        for (int u = 0; u < 8; u++) {
            const int j = jt + u;
            u64 h2a = pack2(hA[u]);
            u64 h2b = pack2(hB[u]);
            if (pf) {
                hA[u] = hpA[(size_t)(jt + 8 + u) * HH];
                hB[u] = hpB[(size_t)(jt + 8 + u) * HH];
            }
#pragma unroll
            for (int g = 0; g < 4; g++) {
                ulonglong2 q = *(const ulonglong2*)(att + g * 4096 + j * 4);
                ffma2(accA[2 * g], q.x, h2a); ffma2(accA[2 * g + 1], q.y, h2a);
                ffma2(accB[2 * g], q.x, h2b); ffma2(accB[2 * g + 1], q.y, h2b);
            }
        }
    }

    float* ob = out + ((size_t)b * NN + i0) * HH + tid;
#pragma unroll
    for (int p = 0; p < 8; p++) {
        float2 vA = unpack2(accA[p]);
        float2 vB = unpack2(accB[p]);
        float i0v = rinv[2 * p], i1v = rinv[2 * p + 1];
        ob[(size_t)(2 * p) * HH]           = fmaxf(vA.x * i0v, 0.f);
        ob[(size_t)(2 * p + 1) * HH]       = fmaxf(vA.y * i1v, 0.f);
        ob[(size_t)(2 * p) * HH + 128]     = fmaxf(vB.x * i0v, 0.f);
        ob[(size_t)(2 * p + 1) * HH + 128] = fmaxf(vB.y * i1v, 0.f);
    }
}

// ---------------- pooling partials: 8 segments of 128 rows ----------------
__global__ __launch_bounds__(256) void pool_partial_kernel(
    const float* __restrict__ x, float* __restrict__ pool)
{
    const int seg = blockIdx.x, b = blockIdx.y, c = threadIdx.x;
    const float* xb = x + ((size_t)b * NN + seg * 128) * HH + c;
    float s = 0.f, m = -3.4e38f;
#pragma unroll 8
    for (int n = 0; n < 128; n++) {
        float v = xb[(size_t)n * HH];
        s += v;
        m = fmaxf(m, v);
    }
    float* pb = pool + ((size_t)b * 8 + seg) * 2 * HH;
    pb[c] = s;
    pb[HH + c] = m;
}

// ---------------- combine + 2-layer MLP ----------------
__global__ __launch_bounds__(256) void mlp_kernel(
    const float* __restrict__ pool, const float* __restrict__ W1,
    const float* __restrict__ b1, const float* __restrict__ W2,
    const float* __restrict__ b2, float* __restrict__ gout)
{
    __shared__ float g0[HH];
    __shared__ float t1[HH];
    const int b = blockIdx.x, c = threadIdx.x;
    const float* pb = pool + (size_t)b * 8 * 2 * HH;

    float s = 0.f, m = -3.4e38f;
#pragma unroll
    for (int seg = 0; seg < 8; seg++) {
        s += pb[seg * 2 * HH + c];
        m = fmaxf(m, pb[seg * 2 * HH + HH + c]);
    }
    g0[c] = s * (1.0f / NN) + m;
    __syncthreads();

    float a = b1[c];
#pragma unroll 4
    for (int k = 0; k < HH; k++) a += g0[k] * W1[k * HH + c];
    t1[c] = fmaxf(a, 0.f);
    __syncthreads();

    float a2 = b2[c];
#pragma unroll 4
    for (int k = 0; k < HH; k++) a2 += t1[k] * W2[k * HH + c];
    gout[b * HH + c] = a2;
}

// ---------------- launch ----------------
extern "C" void kernel_launch(void* const* d_in, const int* in_sizes, int n_in,
                              void* d_out, int out_size)
{
    const float* nf   = (const float*)d_in[0];
    const float* adj  = (const float*)d_in[1];
    const float* embW = (const float*)d_in[2];
    const float* embB = (const float*)d_in[3];
    const float* W0   = (const float*)d_in[4];
    const float* a10  = (const float*)d_in[5];
    const float* a20  = (const float*)d_in[6];
    const float* W1   = (const float*)d_in[7];
    const float* a11  = (const float*)d_in[8];
    const float* a21  = (const float*)d_in[9];
    const float* gW1  = (const float*)d_in[10];
    const float* gb1  = (const float*)d_in[11];
    const float* gW2  = (const float*)d_in[12];
    const float* gb2  = (const float*)d_in[13];

    float* out  = (float*)d_out;
    float* xout = out;                              // [B,N,H]
    float* gout = out + (size_t)BB * NN * HH;       // [B,H]

    float *xb, *hb, *s1b, *s2b, *poolb;
    uint32_t* maskb;
    cudaGetSymbolAddress((void**)&xb,    g_x);
    cudaGetSymbolAddress((void**)&hb,    g_h);
    cudaGetSymbolAddress((void**)&s1b,   g_s1);
    cudaGetSymbolAddress((void**)&s2b,   g_s2);
    cudaGetSymbolAddress((void**)&maskb, g_mask);
    cudaGetSymbolAddress((void**)&poolb, g_pool);

    cudaFuncSetAttribute(att_kernel, cudaFuncAttributeMaxDynamicSharedMemorySize, 64 * 1024);

    const int mrows = BB * NN;
    dim3 blk128(128);

    pack_adj_kernel<<<BB * NN * NN / 256, 256>>>(adj, maskb);
    embed_kernel<<<mrows / 16, blk128>>>(nf, embW, embB, xb);

    // layer 0
    gemm_s1s2_kernel<<<mrows / 16, blk128>>>(xb, W0, a10, a20, hb, s1b, s2b);
    att_kernel<<<dim3(NN / 16, BB), blk128, 64 * 1024>>>(maskb, hb, s1b, s2b, xb);

    // layer 1
    gemm_s1s2_kernel<<<mrows / 16, blk128>>>(xb, W1, a11, a21, hb, s1b, s2b);
    att_kernel<<<dim3(NN / 16, BB), blk128, 64 * 1024>>>(maskb, hb, s1b, s2b, xout);

    // pooling + MLP head
    pool_partial_kernel<<<dim3(8, BB), 256>>>(xout, poolb);
    mlp_kernel<<<BB, 256>>>(poolb, gW1, gb1, gW2, gb2, gout);
}